// round 4
// baseline (speedup 1.0000x reference)
#include <cuda_runtime.h>
#include <cstdint>
#include <cstddef>
#include <math.h>

#define DI __device__ __forceinline__

static constexpr int NR = 8192;
static constexpr int HD = 256;
static constexpr int BM = 128;
static constexpr int BN = 128;
static constexpr int BK = 64;
static constexpr int STAGES = 3;
static constexpr int NTHREADS = 512;   // 16 warps: 4 (M) x 4 (N)

// A stage: 128 rows x 68 floats (64 data + 4 pad)
// B stage:  64 rows x 136 floats (128 data + 8 pad)
static constexpr int A_ROW_F = 68;
static constexpr int B_ROW_F = 136;
static constexpr int STAGE_F = 8704;                  // floats per stage (both equal)
static constexpr int SMEM_DEG_B = 512;
static constexpr int SMEM_TOTAL = SMEM_DEG_B + 2 * STAGES * STAGE_F * 4;  // 209408

__device__ float g_P[(size_t)NR * HD];                // inputs @ W, stored as tf32-rounded bits

DI uint32_t smem_u32(const void* p) {
    uint32_t a;
    asm("{ .reg .u64 t; cvta.to.shared.u64 t, %1; cvt.u32.u64 %0, t; }" : "=r"(a) : "l"(p));
    return a;
}
DI void cp_async16(uint32_t dst, const void* src) {
    asm volatile("cp.async.cg.shared.global [%0], [%1], 16;" :: "r"(dst), "l"(src) : "memory");
}
DI void cp_commit() { asm volatile("cp.async.commit_group;" ::: "memory"); }
template <int N> DI void cp_wait() { asm volatile("cp.async.wait_group %0;" :: "n"(N) : "memory"); }
DI uint32_t f2tf32(float f) {
    uint32_t u;
    asm("cvt.rna.tf32.f32 %0, %1;" : "=r"(u) : "f"(f));
    return u;
}
DI void mma_tf32(float* d, const uint32_t* a, const uint32_t* b) {
    asm volatile(
        "mma.sync.aligned.m16n8k8.row.col.f32.tf32.tf32.f32 "
        "{%0,%1,%2,%3}, {%4,%5,%6,%7}, {%8,%9}, {%0,%1,%2,%3};"
        : "+f"(d[0]), "+f"(d[1]), "+f"(d[2]), "+f"(d[3])
        : "r"(a[0]), "r"(a[1]), "r"(a[2]), "r"(a[3]), "r"(b[0]), "r"(b[1]));
}

// A tile [BM][BK] from A (row-major lda), B tile [BK][BN] from B (row-major ldb)
DI void load_chunk(float* sA, float* sB, int s,
                   const float* __restrict__ A, int lda, int R0,
                   const float* __restrict__ B, int ldb, int N0,
                   int k0, int tid) {
    uint32_t aAddr = smem_u32(sA + s * STAGE_F);
    uint32_t bAddr = smem_u32(sB + s * STAGE_F);
#pragma unroll
    for (int i = 0; i < 4; ++i) {                      // A: 2048 x 16B
        int idx = tid + i * NTHREADS;
        int r = idx >> 4, c = idx & 15;
        cp_async16(aAddr + (uint32_t)(r * (A_ROW_F * 4) + c * 16),
                   A + (size_t)(R0 + r) * lda + k0 + c * 4);
    }
#pragma unroll
    for (int i = 0; i < 4; ++i) {                      // B: 2048 x 16B
        int idx = tid + i * NTHREADS;
        int r = idx >> 5, c = idx & 31;
        cp_async16(bAddr + (uint32_t)(r * (B_ROW_F * 4) + c * 16),
                   B + (size_t)(k0 + r) * ldb + N0 + c * 4);
    }
}

// MODE 0: g_P[i][h] = tf32_round(sum_k inputs[i][k] * W[k][h])
// MODE 1: out[r][n] = tanh((sum_k adj[r][k]*P[k][n] + P[r][n]) / (rowsum(adj[r])+1) + b[n])
//         (B = g_P already tf32 bits -> no cvt on B fragments)
template <int MODE>
__global__ void __launch_bounds__(NTHREADS, 1)
gemm_gcn(const float* __restrict__ A, const float* __restrict__ Bext,
         float* __restrict__ out, const float* __restrict__ bias) {
    extern __shared__ char smem[];
    float* sdeg = (float*)smem;
    float* sA = (float*)(smem + SMEM_DEG_B);
    float* sB = sA + STAGES * STAGE_F;

    const int tid = threadIdx.x;
    const int lane = tid & 31;
    const int wid = tid >> 5;
    const int wm = wid >> 2;            // 0..3  (M dir, 32 rows each)
    const int wn = wid & 3;             // 0..3  (N dir, 32 cols each)
    const int q = lane >> 2;            // 0..7
    const int c4 = lane & 3;            // 0..3

    const int Mt = blockIdx.x >> 1;
    const int Nt = blockIdx.x & 1;
    const int R0 = Mt * BM;
    const int N0 = Nt * BN;

    const int lda = (MODE == 0) ? HD : NR;
    const float* Bp = (MODE == 0) ? Bext : g_P;
    const int ldb = HD;
    const int NCH = ((MODE == 0) ? HD : NR) / BK;

    float acc[2][4][4];
#pragma unroll
    for (int i = 0; i < 2; ++i)
#pragma unroll
        for (int j = 0; j < 4; ++j)
#pragma unroll
            for (int e = 0; e < 4; ++e) acc[i][j][e] = 0.0f;
    float dsum[2][2];
    dsum[0][0] = dsum[0][1] = dsum[1][0] = dsum[1][1] = 0.0f;

#pragma unroll
    for (int s = 0; s < STAGES - 1; ++s) {
        load_chunk(sA, sB, s, A, lda, R0, Bp, ldb, N0, s * BK, tid);
        cp_commit();
    }

    const int aBase = (wm * 32 + q) * A_ROW_F + c4;    // + mt*16*A_ROW_F + ks*8 (+4)
    const int bBase = c4 * B_ROW_F + (wn * 32 + q);    // + ks*8*B_ROW_F + nt*8 (+4*B_ROW_F)

    for (int kc = 0; kc < NCH; ++kc) {
        const int s = kc % STAGES;
        const int cn = kc + STAGES - 1;
        if (cn < NCH) load_chunk(sA, sB, cn % STAGES, A, lda, R0, Bp, ldb, N0, cn * BK, tid);
        cp_commit();
        cp_wait<STAGES - 1>();
        __syncthreads();

        const float* aS = sA + s * STAGE_F;
        const float* bS = sB + s * STAGE_F;
#pragma unroll
        for (int ks = 0; ks < BK / 8; ++ks) {
            uint32_t af[2][4];
#pragma unroll
            for (int mt = 0; mt < 2; ++mt) {
                int base = aBase + mt * 16 * A_ROW_F + ks * 8;
                float f0 = aS[base];
                float f1 = aS[base + 8 * A_ROW_F];
                float f2 = aS[base + 4];
                float f3 = aS[base + 8 * A_ROW_F + 4];
                if (MODE == 1 && wn == 0) {
                    dsum[mt][0] += f0 + f2;
                    dsum[mt][1] += f1 + f3;
                }
                af[mt][0] = f2tf32(f0);
                af[mt][1] = f2tf32(f1);
                af[mt][2] = f2tf32(f2);
                af[mt][3] = f2tf32(f3);
            }
            uint32_t bf[4][2];
#pragma unroll
            for (int nt = 0; nt < 4; ++nt) {
                int base = bBase + ks * 8 * B_ROW_F + nt * 8;
                if (MODE == 0) {
                    bf[nt][0] = f2tf32(bS[base]);
                    bf[nt][1] = f2tf32(bS[base + 4 * B_ROW_F]);
                } else {
                    bf[nt][0] = __float_as_uint(bS[base]);               // already tf32 bits
                    bf[nt][1] = __float_as_uint(bS[base + 4 * B_ROW_F]);
                }
            }
#pragma unroll
            for (int mt = 0; mt < 2; ++mt)
#pragma unroll
                for (int nt = 0; nt < 4; ++nt)
                    mma_tf32(acc[mt][nt], af[mt], bf[nt]);
        }
        __syncthreads();
    }

    if (MODE == 0) {
        // store tf32-rounded bit patterns so GEMM2 skips all B cvts
#pragma unroll
        for (int mt = 0; mt < 2; ++mt) {
            int rlo = R0 + wm * 32 + mt * 16 + q;
#pragma unroll
            for (int nt = 0; nt < 4; ++nt) {
                int col = N0 + wn * 32 + nt * 8 + 2 * c4;
                float2 vlo, vhi;
                vlo.x = __uint_as_float(f2tf32(acc[mt][nt][0]));
                vlo.y = __uint_as_float(f2tf32(acc[mt][nt][1]));
                vhi.x = __uint_as_float(f2tf32(acc[mt][nt][2]));
                vhi.y = __uint_as_float(f2tf32(acc[mt][nt][3]));
                *(float2*)&g_P[(size_t)rlo * HD + col] = vlo;
                *(float2*)&g_P[(size_t)(rlo + 8) * HD + col] = vhi;
            }
        }
    } else {
        if (wn == 0) {
#pragma unroll
            for (int mt = 0; mt < 2; ++mt) {
#pragma unroll
                for (int h = 0; h < 2; ++h) {
                    float v = dsum[mt][h];
                    v += __shfl_xor_sync(0xffffffffu, v, 1);
                    v += __shfl_xor_sync(0xffffffffu, v, 2);
                    dsum[mt][h] = v;
                }
                if (c4 == 0) {
                    sdeg[wm * 32 + mt * 16 + q] = dsum[mt][0];
                    sdeg[wm * 32 + mt * 16 + q + 8] = dsum[mt][1];
                }
            }
        }
        __syncthreads();
#pragma unroll
        for (int mt = 0; mt < 2; ++mt) {
            int lrow = wm * 32 + mt * 16 + q;
            int rlo = R0 + lrow;
            int rhi = rlo + 8;
            float invlo = 1.0f / (sdeg[lrow] + 1.0f);
            float invhi = 1.0f / (sdeg[lrow + 8] + 1.0f);
#pragma unroll
            for (int nt = 0; nt < 4; ++nt) {
                int col = N0 + wn * 32 + nt * 8 + 2 * c4;
                float2 plo = *(const float2*)&g_P[(size_t)rlo * HD + col];
                float2 phi = *(const float2*)&g_P[(size_t)rhi * HD + col];
                float2 bb = *(const float2*)&bias[col];
                float2 olo, ohi;
                olo.x = tanhf((acc[mt][nt][0] + plo.x) * invlo + bb.x);
                olo.y = tanhf((acc[mt][nt][1] + plo.y) * invlo + bb.y);
                ohi.x = tanhf((acc[mt][nt][2] + phi.x) * invhi + bb.x);
                ohi.y = tanhf((acc[mt][nt][3] + phi.y) * invhi + bb.y);
                *(float2*)&out[(size_t)rlo * HD + col] = olo;
                *(float2*)&out[(size_t)rhi * HD + col] = ohi;
            }
        }
    }
}

extern "C" void kernel_launch(void* const* d_in, const int* in_sizes, int n_in,
                              void* d_out, int out_size) {
    const float* inputs = (const float*)d_in[0];
    const float* adj    = (const float*)d_in[1];
    const float* W      = (const float*)d_in[2];
    const float* b      = (const float*)d_in[3];
    float* out = (float*)d_out;

    cudaFuncSetAttribute(gemm_gcn<0>, cudaFuncAttributeMaxDynamicSharedMemorySize, SMEM_TOTAL);
    cudaFuncSetAttribute(gemm_gcn<1>, cudaFuncAttributeMaxDynamicSharedMemorySize, SMEM_TOTAL);

    gemm_gcn<0><<<(NR / BM) * (HD / BN), NTHREADS, SMEM_TOTAL>>>(inputs, W, nullptr, nullptr);
    gemm_gcn<1><<<(NR / BM) * (HD / BN), NTHREADS, SMEM_TOTAL>>>(adj, nullptr, out, b);
}

// round 5
// speedup vs baseline: 1.1212x; 1.1212x over previous
#include <cuda_runtime.h>
#include <cstdint>
#include <cstddef>
#include <math.h>

#define DI __device__ __forceinline__

static constexpr int NR = 8192;
static constexpr int HD = 256;
static constexpr int BM = 128;
static constexpr int BN = 128;
static constexpr int BK = 64;
static constexpr int STAGES = 3;
static constexpr int NTHREADS = 256;    // 8 warps: 2(M) x 2(N) x 2(K)

static constexpr int A_ROW_F = 68;      // 64 data + 4 pad floats
static constexpr int B_ROW_F = 136;     // 128 data + 8 pad floats
static constexpr int STAGE_F = 8704;    // floats per stage (A: 128x68, B: 64x136 — equal)
static constexpr int SMEM_DEG_B = 512;
static constexpr int SMEM_TOTAL = SMEM_DEG_B + 2 * STAGES * STAGE_F * 4;  // 209408
static constexpr int RED_STRIDE = 130;  // epilogue reduction stride (floats)

__device__ float g_P[(size_t)NR * HD];  // inputs @ W, stored as tf32-rounded bit patterns

DI uint32_t smem_u32(const void* p) {
    uint32_t a;
    asm("{ .reg .u64 t; cvta.to.shared.u64 t, %1; cvt.u32.u64 %0, t; }" : "=r"(a) : "l"(p));
    return a;
}
DI void cp_async16(uint32_t dst, const void* src) {
    asm volatile("cp.async.cg.shared.global [%0], [%1], 16;" :: "r"(dst), "l"(src) : "memory");
}
DI void cp_commit() { asm volatile("cp.async.commit_group;" ::: "memory"); }
template <int N> DI void cp_wait() { asm volatile("cp.async.wait_group %0;" :: "n"(N) : "memory"); }
DI uint32_t f2tf32(float f) {
    uint32_t u;
    asm("cvt.rna.tf32.f32 %0, %1;" : "=r"(u) : "f"(f));
    return u;
}
DI void mma_tf32(float* d, const uint32_t* a, const uint32_t* b) {
    asm volatile(
        "mma.sync.aligned.m16n8k8.row.col.f32.tf32.tf32.f32 "
        "{%0,%1,%2,%3}, {%4,%5,%6,%7}, {%8,%9}, {%0,%1,%2,%3};"
        : "+f"(d[0]), "+f"(d[1]), "+f"(d[2]), "+f"(d[3])
        : "r"(a[0]), "r"(a[1]), "r"(a[2]), "r"(a[3]), "r"(b[0]), "r"(b[1]));
}

DI void load_chunk(float* sA, float* sB, int s,
                   const float* __restrict__ A, int lda, int R0,
                   const float* __restrict__ B, int ldb, int N0,
                   int k0, int tid) {
    uint32_t aAddr = smem_u32(sA + s * STAGE_F);
    uint32_t bAddr = smem_u32(sB + s * STAGE_F);
#pragma unroll
    for (int i = 0; i < 8; ++i) {                      // A: 2048 x 16B
        int idx = tid + i * NTHREADS;
        int r = idx >> 4, c = idx & 15;
        cp_async16(aAddr + (uint32_t)(r * (A_ROW_F * 4) + c * 16),
                   A + (size_t)(R0 + r) * lda + k0 + c * 4);
    }
#pragma unroll
    for (int i = 0; i < 8; ++i) {                      // B: 2048 x 16B
        int idx = tid + i * NTHREADS;
        int r = idx >> 5, c = idx & 31;
        cp_async16(bAddr + (uint32_t)(r * (B_ROW_F * 4) + c * 16),
                   B + (size_t)(k0 + r) * ldb + N0 + c * 4);
    }
}

// Fragment loads for one ks step. MODE 0 -> cvt.rna to tf32; MODE 1 -> raw bits (trunc).
template <int MODE>
DI void load_frags(const float* __restrict__ aS, const float* __restrict__ bS,
                   int aBase, int bBase, int ks,
                   uint32_t af[4][4], uint32_t bf[8][2],
                   float dsum[4][2], bool doDeg) {
#pragma unroll
    for (int mt = 0; mt < 4; ++mt) {
        int base = aBase + mt * 16 * A_ROW_F + ks * 8;
        float f0 = aS[base];
        float f1 = aS[base + 8 * A_ROW_F];
        float f2 = aS[base + 4];
        float f3 = aS[base + 8 * A_ROW_F + 4];
        if (MODE == 1 && doDeg) {
            dsum[mt][0] += f0 + f2;
            dsum[mt][1] += f1 + f3;
        }
        if (MODE == 0) {
            af[mt][0] = f2tf32(f0); af[mt][1] = f2tf32(f1);
            af[mt][2] = f2tf32(f2); af[mt][3] = f2tf32(f3);
        } else {
            af[mt][0] = __float_as_uint(f0); af[mt][1] = __float_as_uint(f1);
            af[mt][2] = __float_as_uint(f2); af[mt][3] = __float_as_uint(f3);
        }
    }
#pragma unroll
    for (int nt = 0; nt < 8; ++nt) {
        int base = bBase + ks * 8 * B_ROW_F + nt * 8;
        float b0 = bS[base];
        float b1 = bS[base + 4 * B_ROW_F];
        if (MODE == 0) {
            bf[nt][0] = f2tf32(b0); bf[nt][1] = f2tf32(b1);
        } else {
            bf[nt][0] = __float_as_uint(b0); bf[nt][1] = __float_as_uint(b1);
        }
    }
}

// MODE 0: g_P = tf32_round(inputs @ W)
// MODE 1: out = tanh((adj @ P + P_selfrow) / (rowsum(adj)+1) + b)
template <int MODE>
__global__ void __launch_bounds__(NTHREADS, 1)
gemm_gcn(const float* __restrict__ A, const float* __restrict__ Bext,
         float* __restrict__ out, const float* __restrict__ bias) {
    extern __shared__ char smem[];
    float* sdeg = (float*)smem;
    float* sA = (float*)(smem + SMEM_DEG_B);
    float* sB = sA + STAGES * STAGE_F;

    const int tid = threadIdx.x;
    const int lane = tid & 31;
    const int wid = tid >> 5;
    const int wm = wid & 1;             // M half (64 rows)
    const int wn = (wid >> 1) & 1;      // N half (64 cols)
    const int wk = wid >> 2;            // K half (32 of 64)
    const int q = lane >> 2;            // 0..7
    const int c4 = lane & 3;            // 0..3

    const int Mt = blockIdx.x >> 1;
    const int Nt = blockIdx.x & 1;
    const int R0 = Mt * BM;
    const int N0 = Nt * BN;

    const int lda = (MODE == 0) ? HD : NR;
    const float* Bp = (MODE == 0) ? Bext : g_P;
    const int ldb = HD;
    const int NCH = ((MODE == 0) ? HD : NR) / BK;
    const bool doDeg = (MODE == 1) && (wn == 0);

    float acc[4][8][4];
#pragma unroll
    for (int i = 0; i < 4; ++i)
#pragma unroll
        for (int j = 0; j < 8; ++j)
#pragma unroll
            for (int e = 0; e < 4; ++e) acc[i][j][e] = 0.0f;
    float dsum[4][2];
#pragma unroll
    for (int i = 0; i < 4; ++i) dsum[i][0] = dsum[i][1] = 0.0f;

    if (tid < BM) sdeg[tid] = 0.0f;

    // prologue: stages 0,1
    load_chunk(sA, sB, 0, A, lda, R0, Bp, ldb, N0, 0, tid);
    cp_commit();
    load_chunk(sA, sB, 1, A, lda, R0, Bp, ldb, N0, BK, tid);
    cp_commit();

    const int aBase = (wm * 64 + q) * A_ROW_F + wk * 32 + c4;
    const int bBase = (wk * 32 + c4) * B_ROW_F + wn * 64 + q;

    for (int kc = 0; kc < NCH; ++kc) {
        if (kc + 2 < NCH) cp_wait<1>(); else cp_wait<0>();
        __syncthreads();                                    // all warps done with stage kc-1
        if (kc + 2 < NCH) {
            load_chunk(sA, sB, (kc + 2) % STAGES, A, lda, R0, Bp, ldb, N0, (kc + 2) * BK, tid);
            cp_commit();
        }

        const float* aS = sA + (kc % STAGES) * STAGE_F;
        const float* bS = sB + (kc % STAGES) * STAGE_F;

        uint32_t af[2][4][4], bf[2][8][2];
        load_frags<MODE>(aS, bS, aBase, bBase, 0, af[0], bf[0], dsum, doDeg);
#pragma unroll
        for (int ks = 0; ks < 4; ++ks) {
            const int c = ks & 1;
            if (ks < 3)
                load_frags<MODE>(aS, bS, aBase, bBase, ks + 1, af[c ^ 1], bf[c ^ 1], dsum, doDeg);
#pragma unroll
            for (int mt = 0; mt < 4; ++mt)
#pragma unroll
                for (int nt = 0; nt < 8; ++nt)
                    mma_tf32(acc[mt][nt], af[c][mt], bf[c][nt]);
        }
    }
    __syncthreads();    // mainloop reads done; smem stages reusable

    // degrees (MODE 1): both K-half warps with wn==0 contribute
    if (doDeg) {
#pragma unroll
        for (int mt = 0; mt < 4; ++mt) {
#pragma unroll
            for (int h = 0; h < 2; ++h) {
                float v = dsum[mt][h];
                v += __shfl_xor_sync(0xffffffffu, v, 1);
                v += __shfl_xor_sync(0xffffffffu, v, 2);
                dsum[mt][h] = v;
            }
            if (c4 == 0) {
                atomicAdd(&sdeg[wm * 64 + mt * 16 + q], dsum[mt][0]);
                atomicAdd(&sdeg[wm * 64 + mt * 16 + q + 8], dsum[mt][1]);
            }
        }
    }

    // split-K reduction through SMEM: wk==1 stores, wk==0 adds
    float* sRed = sA;   // 128 x RED_STRIDE floats = 66560 B < 3 A-stages
    if (wk == 1) {
#pragma unroll
        for (int mt = 0; mt < 4; ++mt) {
            int lrow = wm * 64 + mt * 16 + q;
#pragma unroll
            for (int nt = 0; nt < 8; ++nt) {
                int lcol = wn * 64 + nt * 8 + 2 * c4;
                *(float2*)&sRed[lrow * RED_STRIDE + lcol] = make_float2(acc[mt][nt][0], acc[mt][nt][1]);
                *(float2*)&sRed[(lrow + 8) * RED_STRIDE + lcol] = make_float2(acc[mt][nt][2], acc[mt][nt][3]);
            }
        }
    }
    __syncthreads();
    if (wk == 0) {
#pragma unroll
        for (int mt = 0; mt < 4; ++mt) {
            int lrow = wm * 64 + mt * 16 + q;
            int rlo = R0 + lrow;
            int rhi = rlo + 8;
            float invlo = 0.0f, invhi = 0.0f;
            if (MODE == 1) {
                invlo = 1.0f / (sdeg[lrow] + 1.0f);
                invhi = 1.0f / (sdeg[lrow + 8] + 1.0f);
            }
#pragma unroll
            for (int nt = 0; nt < 8; ++nt) {
                int lcol = wn * 64 + nt * 8 + 2 * c4;
                int col = N0 + lcol;
                float2 r0 = *(const float2*)&sRed[lrow * RED_STRIDE + lcol];
                float2 r1 = *(const float2*)&sRed[(lrow + 8) * RED_STRIDE + lcol];
                float s0 = acc[mt][nt][0] + r0.x;
                float s1 = acc[mt][nt][1] + r0.y;
                float s2 = acc[mt][nt][2] + r1.x;
                float s3 = acc[mt][nt][3] + r1.y;
                if (MODE == 0) {
                    float2 vlo, vhi;
                    vlo.x = __uint_as_float(f2tf32(s0));
                    vlo.y = __uint_as_float(f2tf32(s1));
                    vhi.x = __uint_as_float(f2tf32(s2));
                    vhi.y = __uint_as_float(f2tf32(s3));
                    *(float2*)&g_P[(size_t)rlo * HD + col] = vlo;
                    *(float2*)&g_P[(size_t)rhi * HD + col] = vhi;
                } else {
                    float2 plo = *(const float2*)&g_P[(size_t)rlo * HD + col];
                    float2 phi = *(const float2*)&g_P[(size_t)rhi * HD + col];
                    float2 bb = *(const float2*)&bias[col];
                    float2 olo, ohi;
                    olo.x = tanhf((s0 + plo.x) * invlo + bb.x);
                    olo.y = tanhf((s1 + plo.y) * invlo + bb.y);
                    ohi.x = tanhf((s2 + phi.x) * invhi + bb.x);
                    ohi.y = tanhf((s3 + phi.y) * invhi + bb.y);
                    *(float2*)&out[(size_t)rlo * HD + col] = olo;
                    *(float2*)&out[(size_t)rhi * HD + col] = ohi;
                }
            }
        }
    }
}

extern "C" void kernel_launch(void* const* d_in, const int* in_sizes, int n_in,
                              void* d_out, int out_size) {
    const float* inputs = (const float*)d_in[0];
    const float* adj    = (const float*)d_in[1];
    const float* W      = (const float*)d_in[2];
    const float* b      = (const float*)d_in[3];
    float* out = (float*)d_out;

    cudaFuncSetAttribute(gemm_gcn<0>, cudaFuncAttributeMaxDynamicSharedMemorySize, SMEM_TOTAL);
    cudaFuncSetAttribute(gemm_gcn<1>, cudaFuncAttributeMaxDynamicSharedMemorySize, SMEM_TOTAL);

    gemm_gcn<0><<<(NR / BM) * (HD / BN), NTHREADS, SMEM_TOTAL>>>(inputs, W, nullptr, nullptr);
    gemm_gcn<1><<<(NR / BM) * (HD / BN), NTHREADS, SMEM_TOTAL>>>(adj, nullptr, out, b);
}